// round 17
// baseline (speedup 1.0000x reference)
#include <cuda_runtime.h>
#include <cuda_fp16.h>
#include <cstdint>

// Problem constants (fixed by the dataset)
#define NU 100000
#define NI 50000
#define NT (NU + NI)        // 150000 total nodes
#define D  64               // factors
#define D4 (D / 4)          // 16 float4 per f32 row
#define NLAYERS 3
#define NNZ_MAX 4800000

#define SCAN_THREADS 1024
#define SCAN_ITEMS   4
#define SCAN_CHUNK   (SCAN_THREADS * SCAN_ITEMS)          // 4096
#define SCAN_SHIFT   12                                   // log2(SCAN_CHUNK)
#define SCAN_NB      ((NT + SCAN_CHUNK - 1) / SCAN_CHUNK) // 37

// Static device scratch (allocation is forbidden; device globals zero-init)
__device__ __half g_h0[(size_t)NT * D];    // e0 (fp16)
__device__ __half g_h1[(size_t)NT * D];    // e1 (fp16)
__device__ __half g_h2[(size_t)NT * D];    // e2 (fp16)
__device__ int2   g_csr[NNZ_MAX];          // {col, val_bits} in CSR order
__device__ int    g_cnt[NT];               // per-row degree counts (reset by scan)
__device__ int    g_rowptr[NT];            // block-local exclusive prefix
__device__ int    g_fill[NT];              // scatter fill cursors (reset by scan)
__device__ int    g_bsum[SCAN_NB];         // exclusive-scanned chunk totals
__device__ int    g_done;                  // last-block-done counter (reset in A)

__device__ __forceinline__ float2 h2f(unsigned u) {
    __half2 h = *reinterpret_cast<__half2*>(&u);
    return __half22float2(h);
}
__device__ __forceinline__ unsigned f2h(float a, float b) {
    __half2 h = __floats2half2_rn(a, b);
    return *reinterpret_cast<unsigned*>(&h);
}

// ---------------------------------------------------------------------------
// A: fused init + hist.
//   i < total4 : g_h0[i] = fp16(concat(ue,ie)[i]); acc[i] = concat[i]
//   i < nnz    : atomicAdd(g_cnt[row[i]], 1)
// Streaming init traffic overlaps the atomic-ALU-bound histogram.
// g_cnt is 0 on entry: zero-initialized before replay 0, and the scan kernel
// consumes-and-resets it within every replay.
// ---------------------------------------------------------------------------
__global__ void lgcn_init_hist(const float* __restrict__ ue,
                               const float* __restrict__ ie,
                               float* __restrict__ acc,
                               const int* __restrict__ row,
                               int nnz) {
    int i = blockIdx.x * blockDim.x + threadIdx.x;
    const int total4 = NT * D4;
    const int user4  = NU * D4;
    if (i == 0) g_done = 0;
    if (i < total4) {
        float4 v;
        if (i < user4) v = reinterpret_cast<const float4*>(ue)[i];
        else           v = reinterpret_cast<const float4*>(ie)[i - user4];
        reinterpret_cast<float4*>(acc)[i] = v;
        uint2 h;
        h.x = f2h(v.x, v.y);
        h.y = f2h(v.z, v.w);
        reinterpret_cast<uint2*>(g_h0)[i] = h;
    }
    if (i < nnz) atomicAdd(&g_cnt[row[i]], 1);
}

// ---------------------------------------------------------------------------
// scan: per-chunk exclusive prefix (g_rowptr) + chunk totals; the LAST
// finishing block (thread 0 ONLY — fully uniform control flow, no barrier
// in divergent code) serially exclusive-scans the 37 chunk totals.
// Also consumes-and-resets g_cnt / g_fill for this replay's scatter.
// Final rowptr[r] = g_rowptr[r] + g_bsum[r >> SCAN_SHIFT] (resolved inline).
// ---------------------------------------------------------------------------
__global__ void lgcn_scan() {
    __shared__ int sh[SCAN_THREADS];
    int t = threadIdx.x;
    int base = blockIdx.x * SCAN_CHUNK + t * SCAN_ITEMS;
    int v[SCAN_ITEMS];
    int s = 0;
#pragma unroll
    for (int j = 0; j < SCAN_ITEMS; j++) {
        int idx = base + j;
        v[j] = (idx < NT) ? g_cnt[idx] : 0;
        if (idx < NT) { g_cnt[idx] = 0; g_fill[idx] = 0; }   // reset for next use
        s += v[j];
    }
    sh[t] = s;
    __syncthreads();
    for (int off = 1; off < SCAN_THREADS; off <<= 1) {       // uniform barriers
        int x = sh[t];
        int y = (t >= off) ? sh[t - off] : 0;
        __syncthreads();
        sh[t] = x + y;
        __syncthreads();
    }
    int excl = sh[t] - s;
#pragma unroll
    for (int j = 0; j < SCAN_ITEMS; j++) {
        int idx = base + j;
        if (idx < NT) g_rowptr[idx] = excl;
        excl += v[j];
    }
    if (t == SCAN_THREADS - 1) g_bsum[blockIdx.x] = sh[SCAN_THREADS - 1];

    // last-block-done: thread 0 of the final block scans the 37 totals
    // serially. No barriers below this point -> no divergent-barrier UB.
    __threadfence();
    if (t == 0) {
        if (atomicAdd(&g_done, 1) == gridDim.x - 1) {
            int vals[SCAN_NB];
            volatile int* bs = g_bsum;
#pragma unroll
            for (int b = 0; b < SCAN_NB; b++) vals[b] = bs[b];  // independent loads
            int run = 0;
#pragma unroll
            for (int b = 0; b < SCAN_NB; b++) {
                int x = vals[b];
                g_bsum[b] = run;                                 // exclusive
                run += x;
            }
            __threadfence();
        }
    }
}

// ---------------------------------------------------------------------------
// scatter edges into CSR order (rowptr resolved inline with bsum)
// ---------------------------------------------------------------------------
__global__ void lgcn_scatter(const int* __restrict__ row,
                             const int* __restrict__ col,
                             const float* __restrict__ val,
                             int nnz) {
    int e = blockIdx.x * blockDim.x + threadIdx.x;
    if (e >= nnz) return;
    int r = row[e];
    int base = g_rowptr[r] + g_bsum[r >> SCAN_SHIFT];
    int pos  = base + atomicAdd(&g_fill[r], 1);
    g_csr[pos] = make_int2(col[e], __float_as_int(val[e]));
}

// ---------------------------------------------------------------------------
// CSR SpMM: fp16 gather (128B/row = 1 L2 line), f32 register accumulate.
// 16 lanes per row; each lane owns 4 dims (8B of the fp16 row).
//   layer 0: h1[r] = sum val*h0[col]
//   layer 1: h2[r] = sum val*h1[col]
//   layer 2: no next store; acc[r] = 0.25*(acc[r] + h1[r] + h2[r] + sum)
// Edge pairs loaded 16-wide with next-chunk prefetch; shfl uses the 16-lane
// GROUP member mask (tails differ between the two groups of a warp).
// Buffers resolved from __device__ symbols IN DEVICE CODE (host-side symbol
// addresses are host shadows; ATS makes that silently wrong on GB300).
// ---------------------------------------------------------------------------
__global__ void lgcn_spmm_csr(float* __restrict__ acc, int layer, int nnz) {
    const __half* __restrict__ cur  = (layer == 0) ? g_h0 :
                                      (layer == 1) ? g_h1 : g_h2;
    __half*       __restrict__ next = (layer == 0) ? g_h1 : g_h2;

    int t   = blockIdx.x * blockDim.x + threadIdx.x;
    int r   = t >> 4;          // row
    int seg = t & 15;          // 8B segment within the 128B fp16 row
    if (r >= NT) return;
    unsigned gmask = 0xFFFFu << (threadIdx.x & 16);

    int start = g_rowptr[r] + g_bsum[r >> SCAN_SHIFT];
    int end   = (r + 1 < NT) ? (g_rowptr[r + 1] + g_bsum[(r + 1) >> SCAN_SHIFT])
                             : nnz;

    float s0 = 0.f, s1 = 0.f, s2 = 0.f, s3 = 0.f;
    const uint2* cur2 = reinterpret_cast<const uint2*>(cur);

    int k = start;
    int2 cv = make_int2(0, 0);
    if (k + seg < end) cv = __ldg(&g_csr[k + seg]);

    for (; k + 16 <= end; ) {            // full 16-edge chunks, prefetched
        int2 use = cv;
        int kn = k + 16;
        if (kn + seg < end) cv = __ldg(&g_csr[kn + seg]);
#pragma unroll
        for (int j = 0; j < 16; j++) {
            int   c = __shfl_sync(gmask, use.x, j, 16);
            float v = __int_as_float(__shfl_sync(gmask, use.y, j, 16));
            uint2 h = __ldg(cur2 + (size_t)c * 16 + seg);
            float2 f0 = h2f(h.x), f1 = h2f(h.y);
            s0 += v * f0.x; s1 += v * f0.y; s2 += v * f1.x; s3 += v * f1.y;
        }
        k = kn;
    }
    int rem = end - k;                    // tail 0..15, uniform within group
    for (int j = 0; j < rem; j++) {
        int   c = __shfl_sync(gmask, cv.x, j, 16);
        float v = __int_as_float(__shfl_sync(gmask, cv.y, j, 16));
        uint2 h = __ldg(cur2 + (size_t)c * 16 + seg);
        float2 f0 = h2f(h.x), f1 = h2f(h.y);
        s0 += v * f0.x; s1 += v * f0.y; s2 += v * f1.x; s3 += v * f1.y;
    }

    size_t o = (size_t)r * 16 + seg;      // uint2 index == float4 index
    if (layer < 2) {
        uint2 h;
        h.x = f2h(s0, s1);
        h.y = f2h(s2, s3);
        reinterpret_cast<uint2*>(next)[o] = h;
    } else {
        // acc = 0.25 * (e0(acc) + e1(h1) + e2(h2) + s)
        uint2 e1 = reinterpret_cast<const uint2*>(g_h1)[o];
        uint2 e2 = reinterpret_cast<const uint2*>(g_h2)[o];
        float2 a1 = h2f(e1.x), b1 = h2f(e1.y);
        float2 a2 = h2f(e2.x), b2 = h2f(e2.y);
        float4 a = reinterpret_cast<float4*>(acc)[o];
        a.x = 0.25f * (a.x + a1.x + a2.x + s0);
        a.y = 0.25f * (a.y + a1.y + a2.y + s1);
        a.z = 0.25f * (a.z + b1.x + b2.x + s2);
        a.w = 0.25f * (a.w + b1.y + b2.y + s3);
        reinterpret_cast<float4*>(acc)[o] = a;
    }
}

// ---------------------------------------------------------------------------
// launch
// Inputs (metadata order): user_emb f32 [NU*D], item_emb f32 [NI*D],
//                          adj_row i32 [NNZ], adj_col i32 [NNZ], adj_val f32 [NNZ]
// Output: mean_emb f32 [NT*D] (users then items)
// Launch order: A(0) scan(1) scatter(2) spmm(3,4,5) -> ncu idx 3 = spmm L0
// ---------------------------------------------------------------------------
extern "C" void kernel_launch(void* const* d_in, const int* in_sizes, int n_in,
                              void* d_out, int out_size) {
    const float* ue   = (const float*)d_in[0];
    const float* ie   = (const float*)d_in[1];
    const int*   arow = (const int*)d_in[2];
    const int*   acol = (const int*)d_in[3];
    const float* aval = (const float*)d_in[4];
    float* acc = (float*)d_out;

    int nnz = in_sizes[2];
    if (nnz > NNZ_MAX) nnz = NNZ_MAX;   // static scratch bound (dataset-fixed)

    const int THREADS = 256;
    const int total4  = NT * D4;                            // 2.4M
    int workA = (nnz > total4) ? nnz : total4;              // 4.8M
    const int gridA    = (workA + THREADS - 1) / THREADS;
    const int gridEdge = (nnz + THREADS - 1) / THREADS;
    const int gridSpmm = (NT * 16 + THREADS - 1) / THREADS;

    lgcn_init_hist<<<gridA, THREADS>>>(ue, ie, acc, arow, nnz);
    lgcn_scan<<<SCAN_NB, SCAN_THREADS>>>();
    lgcn_scatter<<<gridEdge, THREADS>>>(arow, acol, aval, nnz);

    for (int l = 0; l < NLAYERS; l++)
        lgcn_spmm_csr<<<gridSpmm, THREADS>>>(acc, l, nnz);
}